// round 1
// baseline (speedup 1.0000x reference)
#include <cuda_runtime.h>
#include <cstdint>

// GraphAttention: V=500000, D=128, B=4096, T=3, K=64
// rows = B*3 = 12288; per row:
//   node = emb[node_id]                       (512 B gather)
//   att[k] = dot(neigh_k, node)/15  if mask   (512 B gather each, skipped if mask==0)
//   out = LayerNorm(node + sum_k att[k]*neigh_k) * gamma + beta

#define NUM_ROWS  (4096 * 3)
#define KNEIGH    64
#define DDIM      128
#define INV_ATT_SCALE (1.0f / 15.0f)
#define LN_EPS    1e-5f

__global__ __launch_bounds__(256)
void graph_attention_kernel(const int*   __restrict__ node_ids,      // [B,3]
                            const int*   __restrict__ neighbor_ids,  // [B,3,K]
                            const int*   __restrict__ neighbor_mask, // [B,3,K]
                            const float* __restrict__ emb,           // [V,D]
                            const float* __restrict__ gamma,         // [D]
                            const float* __restrict__ beta,          // [D]
                            float*       __restrict__ out)           // [B,3,D]
{
    const int warps_per_block = blockDim.x >> 5;
    const int row  = blockIdx.x * warps_per_block + (threadIdx.x >> 5);
    const int lane = threadIdx.x & 31;
    if (row >= NUM_ROWS) return;

    const float4* __restrict__ embv = reinterpret_cast<const float4*>(emb);

    // Gather node embedding (each lane owns 4 contiguous floats)
    const int nid = node_ids[row];
    const float4 node = embv[(size_t)nid * 32 + lane];

    float4 acc = make_float4(0.f, 0.f, 0.f, 0.f);

    const int* __restrict__ nids  = neighbor_ids  + (size_t)row * KNEIGH;
    const int* __restrict__ nmask = neighbor_mask + (size_t)row * KNEIGH;

    #pragma unroll 4
    for (int k = 0; k < KNEIGH; ++k) {
        // mask is uniform across the warp (scalar per k) -> no divergence
        if (nmask[k] != 0) {
            const int nb = nids[k];
            const float4 n4 = embv[(size_t)nb * 32 + lane];

            // partial dot over this lane's 4 elements
            float p = n4.x * node.x + n4.y * node.y + n4.z * node.z + n4.w * node.w;
            // warp-level reduction (all lanes end with the full dot)
            p += __shfl_xor_sync(0xffffffffu, p, 16);
            p += __shfl_xor_sync(0xffffffffu, p, 8);
            p += __shfl_xor_sync(0xffffffffu, p, 4);
            p += __shfl_xor_sync(0xffffffffu, p, 2);
            p += __shfl_xor_sync(0xffffffffu, p, 1);

            const float att = p * INV_ATT_SCALE;
            acc.x += att * n4.x;
            acc.y += att * n4.y;
            acc.z += att * n4.z;
            acc.w += att * n4.w;
        }
    }

    // x = node + att_out
    float4 x;
    x.x = node.x + acc.x;
    x.y = node.y + acc.y;
    x.z = node.z + acc.z;
    x.w = node.w + acc.w;

    // mean over D=128
    float s = x.x + x.y + x.z + x.w;
    s += __shfl_xor_sync(0xffffffffu, s, 16);
    s += __shfl_xor_sync(0xffffffffu, s, 8);
    s += __shfl_xor_sync(0xffffffffu, s, 4);
    s += __shfl_xor_sync(0xffffffffu, s, 2);
    s += __shfl_xor_sync(0xffffffffu, s, 1);
    const float mu = s * (1.0f / DDIM);

    // variance
    const float dx0 = x.x - mu, dx1 = x.y - mu, dx2 = x.z - mu, dx3 = x.w - mu;
    float q = dx0 * dx0 + dx1 * dx1 + dx2 * dx2 + dx3 * dx3;
    q += __shfl_xor_sync(0xffffffffu, q, 16);
    q += __shfl_xor_sync(0xffffffffu, q, 8);
    q += __shfl_xor_sync(0xffffffffu, q, 4);
    q += __shfl_xor_sync(0xffffffffu, q, 2);
    q += __shfl_xor_sync(0xffffffffu, q, 1);
    const float var = q * (1.0f / DDIM);
    const float r = rsqrtf(var + LN_EPS);

    const float4 g = reinterpret_cast<const float4*>(gamma)[lane];
    const float4 b = reinterpret_cast<const float4*>(beta)[lane];

    float4 o;
    o.x = dx0 * r * g.x + b.x;
    o.y = dx1 * r * g.y + b.y;
    o.z = dx2 * r * g.z + b.z;
    o.w = dx3 * r * g.w + b.w;

    reinterpret_cast<float4*>(out)[(size_t)row * 32 + lane] = o;
}

extern "C" void kernel_launch(void* const* d_in, const int* in_sizes, int n_in,
                              void* d_out, int out_size)
{
    const int*   node_ids      = (const int*)  d_in[0];
    const int*   neighbor_ids  = (const int*)  d_in[1];
    const int*   neighbor_mask = (const int*)  d_in[2];
    const float* emb           = (const float*)d_in[3];
    const float* gamma         = (const float*)d_in[4];
    const float* beta          = (const float*)d_in[5];
    float*       out           = (float*)d_out;

    const int threads = 256;                   // 8 warps/block
    const int warps_per_block = threads / 32;
    const int blocks = (NUM_ROWS + warps_per_block - 1) / warps_per_block;

    graph_attention_kernel<<<blocks, threads>>>(node_ids, neighbor_ids, neighbor_mask,
                                                emb, gamma, beta, out);
}

// round 2
// speedup vs baseline: 1.6753x; 1.6753x over previous
#include <cuda_runtime.h>
#include <cstdint>

// GraphAttention: V=500000, D=128, B=4096, T=3, K=64
// rows = B*3 = 12288
// Strategy: one warp per row. Warp-level compaction of active (mask!=0)
// neighbor ids into a per-warp smem list -> dense, branch-free inner loop
// processing 8 neighbors per chunk with 8 batched LDG.128 (MLP=8).

#define NUM_ROWS  (4096 * 3)
#define KNEIGH    64
#define DDIM      128
#define INV_ATT_SCALE (1.0f / 15.0f)
#define LN_EPS    1e-5f
#define WARPS_PER_BLOCK 8
#define CHUNK 8

__device__ __forceinline__ float warp_sum(float v) {
    v += __shfl_xor_sync(0xffffffffu, v, 16);
    v += __shfl_xor_sync(0xffffffffu, v, 8);
    v += __shfl_xor_sync(0xffffffffu, v, 4);
    v += __shfl_xor_sync(0xffffffffu, v, 2);
    v += __shfl_xor_sync(0xffffffffu, v, 1);
    return v;
}

__global__ __launch_bounds__(WARPS_PER_BLOCK * 32)
void graph_attention_kernel(const int*   __restrict__ node_ids,      // [B,3]
                            const int*   __restrict__ neighbor_ids,  // [B,3,K]
                            const int*   __restrict__ neighbor_mask, // [B,3,K]
                            const float* __restrict__ emb,           // [V,D]
                            const float* __restrict__ gamma,         // [D]
                            const float* __restrict__ beta,          // [D]
                            float*       __restrict__ out)           // [B,3,D]
{
    __shared__ int s_act[WARPS_PER_BLOCK][KNEIGH];

    const int w    = threadIdx.x >> 5;
    const int lane = threadIdx.x & 31;
    const int row  = blockIdx.x * WARPS_PER_BLOCK + w;   // grid sized exactly

    const float4* __restrict__ embv = reinterpret_cast<const float4*>(emb);

    // node embedding: each lane owns 4 contiguous floats
    const int nid = node_ids[row];
    const float4 node = embv[(size_t)nid * 32 + lane];

    // ---- warp-level compaction of active neighbors ----
    const int* __restrict__ nids  = neighbor_ids  + (size_t)row * KNEIGH;
    const int* __restrict__ nmask = neighbor_mask + (size_t)row * KNEIGH;

    const int m0  = nmask[lane];
    const int m1  = nmask[lane + 32];
    const int id0 = nids[lane];
    const int id1 = nids[lane + 32];

    const unsigned full = 0xffffffffu;
    const unsigned b0 = __ballot_sync(full, m0 != 0);
    const unsigned b1 = __ballot_sync(full, m1 != 0);
    const int c0  = __popc(b0);
    const int cnt = c0 + __popc(b1);
    const unsigned lt = (1u << lane) - 1u;

    if (m0) s_act[w][__popc(b0 & lt)]      = id0;
    if (m1) s_act[w][c0 + __popc(b1 & lt)] = id1;
    __syncwarp(full);

    // ---- dense inner loop: 8 batched gathers per chunk ----
    float4 acc = make_float4(0.f, 0.f, 0.f, 0.f);

    int i = 0;
    for (; i + CHUNK <= cnt; i += CHUNK) {
        float4 n4[CHUNK];
        #pragma unroll
        for (int j = 0; j < CHUNK; ++j) {
            const int nb = s_act[w][i + j];
            n4[j] = embv[(size_t)nb * 32 + lane];
        }

        float p[CHUNK];
        #pragma unroll
        for (int j = 0; j < CHUNK; ++j)
            p[j] = n4[j].x * node.x + n4[j].y * node.y
                 + n4[j].z * node.z + n4[j].w * node.w;

        #pragma unroll
        for (int j = 0; j < CHUNK; ++j)
            p[j] = warp_sum(p[j]);   // 8 independent butterfly chains interleave

        #pragma unroll
        for (int j = 0; j < CHUNK; ++j) {
            const float att = p[j] * INV_ATT_SCALE;
            acc.x += att * n4[j].x;
            acc.y += att * n4[j].y;
            acc.z += att * n4[j].z;
            acc.w += att * n4[j].w;
        }
    }
    // remainder (< CHUNK)
    for (; i < cnt; ++i) {
        const int nb = s_act[w][i];
        const float4 n4 = embv[(size_t)nb * 32 + lane];
        float p = n4.x * node.x + n4.y * node.y + n4.z * node.z + n4.w * node.w;
        p = warp_sum(p);
        const float att = p * INV_ATT_SCALE;
        acc.x += att * n4.x;
        acc.y += att * n4.y;
        acc.z += att * n4.z;
        acc.w += att * n4.w;
    }

    // ---- x = node + att_out, then LayerNorm over D=128 ----
    float4 x;
    x.x = node.x + acc.x;
    x.y = node.y + acc.y;
    x.z = node.z + acc.z;
    x.w = node.w + acc.w;

    const float mu = warp_sum(x.x + x.y + x.z + x.w) * (1.0f / DDIM);

    const float dx0 = x.x - mu, dx1 = x.y - mu, dx2 = x.z - mu, dx3 = x.w - mu;
    const float var = warp_sum(dx0*dx0 + dx1*dx1 + dx2*dx2 + dx3*dx3) * (1.0f / DDIM);
    const float r = rsqrtf(var + LN_EPS);

    const float4 g = reinterpret_cast<const float4*>(gamma)[lane];
    const float4 b = reinterpret_cast<const float4*>(beta)[lane];

    float4 o;
    o.x = dx0 * r * g.x + b.x;
    o.y = dx1 * r * g.y + b.y;
    o.z = dx2 * r * g.z + b.z;
    o.w = dx3 * r * g.w + b.w;

    reinterpret_cast<float4*>(out)[(size_t)row * 32 + lane] = o;
}

extern "C" void kernel_launch(void* const* d_in, const int* in_sizes, int n_in,
                              void* d_out, int out_size)
{
    const int*   node_ids      = (const int*)  d_in[0];
    const int*   neighbor_ids  = (const int*)  d_in[1];
    const int*   neighbor_mask = (const int*)  d_in[2];
    const float* emb           = (const float*)d_in[3];
    const float* gamma         = (const float*)d_in[4];
    const float* beta          = (const float*)d_in[5];
    float*       out           = (float*)d_out;

    const int threads = WARPS_PER_BLOCK * 32;
    const int blocks  = NUM_ROWS / WARPS_PER_BLOCK;   // 12288/8 = 1536 exact

    graph_attention_kernel<<<blocks, threads>>>(node_ids, neighbor_ids, neighbor_mask,
                                                emb, gamma, beta, out);
}